// round 15
// baseline (speedup 1.0000x reference)
#include <cuda_runtime.h>
#include <cuda_bf16.h>

// Problem shape (fixed by the dataset)
#define B_DIM 16
#define S_DIM 2048
#define D_DIM 256
#define ROWS  (B_DIM * S_DIM)          // 32768
#define P_ASEM 0.6f
#define Q_ASEM 0.4f
#define MASK_FILL 1e-9f

// Scratch for projected scores (no cudaMalloc allowed)
__device__ float g_si[ROWS];  // si + bias folded in
__device__ float g_sj[ROWS];

// ---------------------------------------------------------------------------
// Kernel 1: dual dot products, 4 rows per warp, masked-row skip (proven R10).
// ---------------------------------------------------------------------------
#define PROJ_RPW 4   // rows per warp

__global__ __launch_bounds__(256) void proj_kernel(const float* __restrict__ x,
                                                   const int*   __restrict__ mask,
                                                   const float* __restrict__ W,
                                                   const float* __restrict__ bias) {
    const int warp = blockIdx.x * (blockDim.x >> 5) + (threadIdx.x >> 5);
    const int lane = threadIdx.x & 31;
    const int row0 = warp * PROJ_RPW;

    int mrow[PROJ_RPW];
#pragma unroll
    for (int r = 0; r < PROJ_RPW; ++r) mrow[r] = __ldg(&mask[row0 + r]);

    const float4* Wi4 = reinterpret_cast<const float4*>(W);            // W[0:256]
    const float4* Wj4 = reinterpret_cast<const float4*>(W + D_DIM);    // W[256:512]

    float4 xv[PROJ_RPW][2];
#pragma unroll
    for (int r = 0; r < PROJ_RPW; ++r) {
        if (mrow[r]) {
            const float4* x4 = reinterpret_cast<const float4*>(x) +
                               (long)(row0 + r) * (D_DIM / 4);
            xv[r][0] = x4[lane];
            xv[r][1] = x4[lane + 32];
        }
    }

    const float4 wi0 = __ldg(&Wi4[lane]);
    const float4 wi1 = __ldg(&Wi4[lane + 32]);
    const float4 wj0 = __ldg(&Wj4[lane]);
    const float4 wj1 = __ldg(&Wj4[lane + 32]);

    float si[PROJ_RPW], sj[PROJ_RPW];
#pragma unroll
    for (int r = 0; r < PROJ_RPW; ++r) {
        if (!mrow[r]) { si[r] = 0.f; sj[r] = 0.f; continue; }
        float a = 0.f, b2 = 0.f;
        a = fmaf(xv[r][0].x, wi0.x, a); a = fmaf(xv[r][0].y, wi0.y, a);
        a = fmaf(xv[r][0].z, wi0.z, a); a = fmaf(xv[r][0].w, wi0.w, a);
        a = fmaf(xv[r][1].x, wi1.x, a); a = fmaf(xv[r][1].y, wi1.y, a);
        a = fmaf(xv[r][1].z, wi1.z, a); a = fmaf(xv[r][1].w, wi1.w, a);
        b2 = fmaf(xv[r][0].x, wj0.x, b2); b2 = fmaf(xv[r][0].y, wj0.y, b2);
        b2 = fmaf(xv[r][0].z, wj0.z, b2); b2 = fmaf(xv[r][0].w, wj0.w, b2);
        b2 = fmaf(xv[r][1].x, wj1.x, b2); b2 = fmaf(xv[r][1].y, wj1.y, b2);
        b2 = fmaf(xv[r][1].z, wj1.z, b2); b2 = fmaf(xv[r][1].w, wj1.w, b2);
        si[r] = a; sj[r] = b2;
    }

#pragma unroll
    for (int off = 16; off > 0; off >>= 1) {
#pragma unroll
        for (int r = 0; r < PROJ_RPW; ++r) {
            if (mrow[r]) {
                si[r] += __shfl_down_sync(0xFFFFFFFFu, si[r], off);
                sj[r] += __shfl_down_sync(0xFFFFFFFFu, sj[r], off);
            }
        }
    }
    if (lane == 0) {
        const float bv = __ldg(bias);
#pragma unroll
        for (int r = 0; r < PROJ_RPW; ++r) {
            if (mrow[r]) {
                g_si[row0 + r] = si[r] + bv;
                g_sj[row0 + r] = sj[r];
            }
        }
    }
}

// ---------------------------------------------------------------------------
// Kernel 2: 512 threads/block (R14 shape), RPB=8 rows/block (R6 MLP).
// Each thread: 8 predicated adj loads up front + ONE sjv/mjv column vector,
// then 8 unified stores (sig_blend with m=0 yields MASK_FILL, so masked rows
// share the same store path — no divergent store sites).
// ---------------------------------------------------------------------------
#define RPB 8   // rows per block

__device__ __forceinline__ float sig_blend(float si, float sjv, int m, float a) {
    float z = si + sjv;
    float s = __fdividef(1.f, 1.f + __expf(-z));
    return m ? fmaf(P_ASEM, s, Q_ASEM * a) : MASK_FILL;
}

__global__ __launch_bounds__(512, 2) void fuse_kernel(const float4* __restrict__ adj4,
                                                      const int*    __restrict__ mask,
                                                      float4*       __restrict__ out4) {
    const unsigned tid   = threadIdx.x;                      // 0..511
    const unsigned row0  = blockIdx.x * RPB;                 // 8 rows, same batch
    const unsigned base  = (row0 << 9) + tid;                // float4 idx of row0[tid]
    const unsigned cbase = ((row0 >> 11) << 9) + tid;        // sj/mask col float4 index

    // per-row masks (uniform across block for each row)
    int mi[RPB];
#pragma unroll
    for (int r = 0; r < RPB; ++r) mi[r] = mask[row0 + r];

    // issue ALL adj loads for unmasked rows up front (predicated, independent)
    float4 av[RPB];
#pragma unroll
    for (int r = 0; r < RPB; ++r) {
        if (mi[r]) av[r] = __ldcs(&adj4[base + (r << 9)]);
        else       av[r] = make_float4(0.f, 0.f, 0.f, 0.f);
    }

    // column vectors: shared by all RPB rows, one load each
    const float4* sj4 = reinterpret_cast<const float4*>(g_sj);
    const int4*   mj4 = reinterpret_cast<const int4*>(mask);
    const float4 sjv = __ldg(&sj4[cbase]);
    const int4   mjv = __ldg(&mj4[cbase]);

#pragma unroll
    for (int r = 0; r < RPB; ++r) {
        const float si = mi[r] ? g_si[row0 + r] : 0.f;
        float4 out;
        out.x = sig_blend(si, sjv.x, mi[r] & mjv.x, av[r].x);
        out.y = sig_blend(si, sjv.y, mi[r] & mjv.y, av[r].y);
        out.z = sig_blend(si, sjv.z, mi[r] & mjv.z, av[r].z);
        out.w = sig_blend(si, sjv.w, mi[r] & mjv.w, av[r].w);
        __stcs(&out4[base + (r << 9)], out);
    }
}

// ---------------------------------------------------------------------------
// Launch
// Inputs (metadata order): 0:x [16,2048,256] f32, 1:adj [16,2048,2048] f32,
//                          2:mask [16,2048] i32, 3:W [1,512] f32, 4:b [1] f32
// Output: [16,2048,2048] f32
// ---------------------------------------------------------------------------
extern "C" void kernel_launch(void* const* d_in, const int* in_sizes, int n_in,
                              void* d_out, int out_size) {
    const float* x    = (const float*)d_in[0];
    const float* adj  = (const float*)d_in[1];
    const int*   mask = (const int*)d_in[2];
    const float* W    = (const float*)d_in[3];
    const float* bias = (const float*)d_in[4];
    float* out = (float*)d_out;

    // Kernel 1: 4 rows/warp, 8 warps/block -> 32 rows/block -> 1024 blocks
    proj_kernel<<<ROWS / (PROJ_RPW * 8), 256>>>(x, mask, W, bias);

    // Kernel 2: one block per 8 output rows -> 4096 blocks of 512 threads
    fuse_kernel<<<ROWS / RPB, 512>>>(reinterpret_cast<const float4*>(adj),
                                     mask,
                                     reinterpret_cast<float4*>(out));
}

// round 16
// speedup vs baseline: 1.0893x; 1.0893x over previous
#include <cuda_runtime.h>
#include <cuda_bf16.h>

// Problem shape (fixed by the dataset)
#define B_DIM 16
#define S_DIM 2048
#define D_DIM 256
#define ROWS  (B_DIM * S_DIM)          // 32768
#define P_ASEM 0.6f
#define Q_ASEM 0.4f
#define MASK_FILL 1e-9f

// Scratch for projected scores (no cudaMalloc allowed)
__device__ float g_si[ROWS];  // si + bias folded in
__device__ float g_sj[ROWS];

// ---------------------------------------------------------------------------
// Kernel 1: dual dot products, 4 rows per warp, masked-row skip (proven R10).
// ---------------------------------------------------------------------------
#define PROJ_RPW 4   // rows per warp

__global__ __launch_bounds__(256) void proj_kernel(const float* __restrict__ x,
                                                   const int*   __restrict__ mask,
                                                   const float* __restrict__ W,
                                                   const float* __restrict__ bias) {
    const int warp = blockIdx.x * (blockDim.x >> 5) + (threadIdx.x >> 5);
    const int lane = threadIdx.x & 31;
    const int row0 = warp * PROJ_RPW;

    int mrow[PROJ_RPW];
#pragma unroll
    for (int r = 0; r < PROJ_RPW; ++r) mrow[r] = __ldg(&mask[row0 + r]);

    const float4* Wi4 = reinterpret_cast<const float4*>(W);            // W[0:256]
    const float4* Wj4 = reinterpret_cast<const float4*>(W + D_DIM);    // W[256:512]

    float4 xv[PROJ_RPW][2];
#pragma unroll
    for (int r = 0; r < PROJ_RPW; ++r) {
        if (mrow[r]) {
            const float4* x4 = reinterpret_cast<const float4*>(x) +
                               (long)(row0 + r) * (D_DIM / 4);
            xv[r][0] = x4[lane];
            xv[r][1] = x4[lane + 32];
        }
    }

    const float4 wi0 = __ldg(&Wi4[lane]);
    const float4 wi1 = __ldg(&Wi4[lane + 32]);
    const float4 wj0 = __ldg(&Wj4[lane]);
    const float4 wj1 = __ldg(&Wj4[lane + 32]);

    float si[PROJ_RPW], sj[PROJ_RPW];
#pragma unroll
    for (int r = 0; r < PROJ_RPW; ++r) {
        if (!mrow[r]) { si[r] = 0.f; sj[r] = 0.f; continue; }
        float a = 0.f, b2 = 0.f;
        a = fmaf(xv[r][0].x, wi0.x, a); a = fmaf(xv[r][0].y, wi0.y, a);
        a = fmaf(xv[r][0].z, wi0.z, a); a = fmaf(xv[r][0].w, wi0.w, a);
        a = fmaf(xv[r][1].x, wi1.x, a); a = fmaf(xv[r][1].y, wi1.y, a);
        a = fmaf(xv[r][1].z, wi1.z, a); a = fmaf(xv[r][1].w, wi1.w, a);
        b2 = fmaf(xv[r][0].x, wj0.x, b2); b2 = fmaf(xv[r][0].y, wj0.y, b2);
        b2 = fmaf(xv[r][0].z, wj0.z, b2); b2 = fmaf(xv[r][0].w, wj0.w, b2);
        b2 = fmaf(xv[r][1].x, wj1.x, b2); b2 = fmaf(xv[r][1].y, wj1.y, b2);
        b2 = fmaf(xv[r][1].z, wj1.z, b2); b2 = fmaf(xv[r][1].w, wj1.w, b2);
        si[r] = a; sj[r] = b2;
    }

#pragma unroll
    for (int off = 16; off > 0; off >>= 1) {
#pragma unroll
        for (int r = 0; r < PROJ_RPW; ++r) {
            if (mrow[r]) {
                si[r] += __shfl_down_sync(0xFFFFFFFFu, si[r], off);
                sj[r] += __shfl_down_sync(0xFFFFFFFFu, sj[r], off);
            }
        }
    }
    if (lane == 0) {
        const float bv = __ldg(bias);
#pragma unroll
        for (int r = 0; r < PROJ_RPW; ++r) {
            if (mrow[r]) {
                g_si[row0 + r] = si[r] + bv;
                g_sj[row0 + r] = sj[r];
            }
        }
    }
}

// ---------------------------------------------------------------------------
// Kernel 2: R14 shape (512 threads, RPB=4, 8192 blocks) with a UNIFIED store
// path: every row goes through sig_blend + one store site (m=0 -> MASK_FILL),
// only the adj load is predicated. No divergent store branches.
// ---------------------------------------------------------------------------
#define RPB 4   // rows per block

__device__ __forceinline__ float sig_blend(float si, float sjv, int m, float a) {
    float z = si + sjv;
    float s = __fdividef(1.f, 1.f + __expf(-z));
    return m ? fmaf(P_ASEM, s, Q_ASEM * a) : MASK_FILL;
}

__global__ __launch_bounds__(512) void fuse_kernel(const float4* __restrict__ adj4,
                                                   const int*    __restrict__ mask,
                                                   float4*       __restrict__ out4) {
    const unsigned tid   = threadIdx.x;                      // 0..511
    const unsigned row0  = blockIdx.x * RPB;                 // 4 rows, same batch
    const unsigned base  = (row0 << 9) + tid;                // float4 idx of row0[tid]
    const unsigned cbase = ((row0 >> 11) << 9) + tid;        // sj/mask col float4 index

    // per-row masks (uniform across block for each row)
    int mi[RPB];
#pragma unroll
    for (int r = 0; r < RPB; ++r) mi[r] = mask[row0 + r];

    // adj loads up front — only the LOAD is predicated
    float4 av[RPB];
#pragma unroll
    for (int r = 0; r < RPB; ++r) {
        if (mi[r]) av[r] = __ldcs(&adj4[base + (r << 9)]);
        else       av[r] = make_float4(0.f, 0.f, 0.f, 0.f);
    }

    // column vectors: shared by all RPB rows, one load each
    const float4* sj4 = reinterpret_cast<const float4*>(g_sj);
    const int4*   mj4 = reinterpret_cast<const int4*>(mask);
    const float4 sjv = __ldg(&sj4[cbase]);
    const int4   mjv = __ldg(&mj4[cbase]);

    // unified compute+store for every row (masked rows produce MASK_FILL)
#pragma unroll
    for (int r = 0; r < RPB; ++r) {
        const float si = mi[r] ? g_si[row0 + r] : 0.f;
        float4 out;
        out.x = sig_blend(si, sjv.x, mi[r] & mjv.x, av[r].x);
        out.y = sig_blend(si, sjv.y, mi[r] & mjv.y, av[r].y);
        out.z = sig_blend(si, sjv.z, mi[r] & mjv.z, av[r].z);
        out.w = sig_blend(si, sjv.w, mi[r] & mjv.w, av[r].w);
        __stcs(&out4[base + (r << 9)], out);
    }
}

// ---------------------------------------------------------------------------
// Launch
// Inputs (metadata order): 0:x [16,2048,256] f32, 1:adj [16,2048,2048] f32,
//                          2:mask [16,2048] i32, 3:W [1,512] f32, 4:b [1] f32
// Output: [16,2048,2048] f32
// ---------------------------------------------------------------------------
extern "C" void kernel_launch(void* const* d_in, const int* in_sizes, int n_in,
                              void* d_out, int out_size) {
    const float* x    = (const float*)d_in[0];
    const float* adj  = (const float*)d_in[1];
    const int*   mask = (const int*)d_in[2];
    const float* W    = (const float*)d_in[3];
    const float* bias = (const float*)d_in[4];
    float* out = (float*)d_out;

    // Kernel 1: 4 rows/warp, 8 warps/block -> 32 rows/block -> 1024 blocks
    proj_kernel<<<ROWS / (PROJ_RPW * 8), 256>>>(x, mask, W, bias);

    // Kernel 2: one block per 4 output rows -> 8192 blocks of 512 threads
    fuse_kernel<<<ROWS / RPB, 512>>>(reinterpret_cast<const float4*>(adj),
                                     mask,
                                     reinterpret_cast<float4*>(out));
}